// round 8
// baseline (speedup 1.0000x reference)
#include <cuda_runtime.h>
#include <cuda_fp16.h>
#include <cstdint>

// Problem constants (fixed: B=8192, D=128)
#define NB 8192
#define ND 128
#define NTILE 64                    // 8192 / 128 tile rows
#define GRID 148                    // one CTA per SM
#define MARGIN 0.5f
#define STRB 272                    // padded row stride in bytes -> conflict-free ldmatrix
#define TILE_BYTES (128 * STRB)     // 34816 per 128x128 fp16 tile

// Device scratch (no allocation allowed)
__device__ __align__(16) __half g_af16[NB * ND];
__device__ float g_posd[NB];
__device__ int   g_lab[NB];
__device__ int   g_maxbits[NB];

// ---------------------------------------------------------------------------
// helpers
// ---------------------------------------------------------------------------
__device__ __forceinline__ uint32_t smem_u32(const void* p) {
    uint32_t a;
    asm("{ .reg .u64 t; cvta.to.shared.u64 t, %1; cvt.u32.u64 %0, t; }" : "=r"(a) : "l"(p));
    return a;
}
__device__ __forceinline__ void cpasync16(uint32_t dst, const void* src) {
    asm volatile("cp.async.cg.shared.global [%0], [%1], 16;" :: "r"(dst), "l"(src));
}
__device__ __forceinline__ void mma16816(float* c, const uint32_t* a, const uint32_t* b) {
    asm volatile(
        "mma.sync.aligned.m16n8k16.row.col.f32.f16.f16.f32 "
        "{%0,%1,%2,%3}, {%4,%5,%6,%7}, {%8,%9}, {%0,%1,%2,%3};"
        : "+f"(c[0]), "+f"(c[1]), "+f"(c[2]), "+f"(c[3])
        : "r"(a[0]), "r"(a[1]), "r"(a[2]), "r"(a[3]), "r"(b[0]), "r"(b[1]));
}
__device__ __forceinline__ void ldsm4(uint32_t* r, uint32_t addr) {
    asm volatile("ldmatrix.sync.aligned.m8n8.x4.shared.b16 {%0,%1,%2,%3}, [%4];"
        : "=r"(r[0]), "=r"(r[1]), "=r"(r[2]), "=r"(r[3]) : "r"(addr));
}

// ---------------------------------------------------------------------------
// Kernel 1: normalize anchors -> fp16; pos_dist; labels; init max.
// Two rows per warp (doubled MLP vs one row/warp).
// ---------------------------------------------------------------------------
__global__ void prep_kernel(const float* __restrict__ anchor,
                            const float* __restrict__ positive,
                            const int* __restrict__ labels) {
    int pair = (blockIdx.x * blockDim.x + threadIdx.x) >> 5;   // warp index
    int lane = threadIdx.x & 31;
    int r0 = pair * 2;
    if (r0 >= NB) return;

    const float4* a0 = reinterpret_cast<const float4*>(anchor   + (size_t)r0 * ND);
    const float4* a1 = reinterpret_cast<const float4*>(anchor   + (size_t)(r0 + 1) * ND);
    const float4* p0 = reinterpret_cast<const float4*>(positive + (size_t)r0 * ND);
    const float4* p1 = reinterpret_cast<const float4*>(positive + (size_t)(r0 + 1) * ND);
    float4 av0 = a0[lane], av1 = a1[lane], pv0 = p0[lane], pv1 = p1[lane];

    float sa0 = av0.x*av0.x + av0.y*av0.y + av0.z*av0.z + av0.w*av0.w;
    float sa1 = av1.x*av1.x + av1.y*av1.y + av1.z*av1.z + av1.w*av1.w;
    float sp0 = pv0.x*pv0.x + pv0.y*pv0.y + pv0.z*pv0.z + pv0.w*pv0.w;
    float sp1 = pv1.x*pv1.x + pv1.y*pv1.y + pv1.z*pv1.z + pv1.w*pv1.w;
    #pragma unroll
    for (int o = 16; o > 0; o >>= 1) {
        sa0 += __shfl_xor_sync(0xffffffffu, sa0, o);
        sa1 += __shfl_xor_sync(0xffffffffu, sa1, o);
        sp0 += __shfl_xor_sync(0xffffffffu, sp0, o);
        sp1 += __shfl_xor_sync(0xffffffffu, sp1, o);
    }
    float ia0 = 1.0f / fmaxf(sqrtf(sa0), 1e-12f);
    float ia1 = 1.0f / fmaxf(sqrtf(sa1), 1e-12f);
    float ip0 = 1.0f / fmaxf(sqrtf(sp0), 1e-12f);
    float ip1 = 1.0f / fmaxf(sqrtf(sp1), 1e-12f);

    float an0[4] = {av0.x*ia0, av0.y*ia0, av0.z*ia0, av0.w*ia0};
    float an1[4] = {av1.x*ia1, av1.y*ia1, av1.z*ia1, av1.w*ia1};
    float pn0[4] = {pv0.x*ip0, pv0.y*ip0, pv0.z*ip0, pv0.w*ip0};
    float pn1[4] = {pv1.x*ip1, pv1.y*ip1, pv1.z*ip1, pv1.w*ip1};

    __half2 h0a; h0a.x = __float2half_rn(an0[0]); h0a.y = __float2half_rn(an0[1]);
    __half2 h0b; h0b.x = __float2half_rn(an0[2]); h0b.y = __float2half_rn(an0[3]);
    __half2 h1a; h1a.x = __float2half_rn(an1[0]); h1a.y = __float2half_rn(an1[1]);
    __half2 h1b; h1b.x = __float2half_rn(an1[2]); h1b.y = __float2half_rn(an1[3]);
    size_t b0 = (size_t)r0 * ND + lane * 4;
    reinterpret_cast<__half2*>(g_af16 + b0)[0] = h0a;
    reinterpret_cast<__half2*>(g_af16 + b0)[1] = h0b;
    reinterpret_cast<__half2*>(g_af16 + b0 + ND)[0] = h1a;
    reinterpret_cast<__half2*>(g_af16 + b0 + ND)[1] = h1b;

    float d20 = 0.0f, d21 = 0.0f;
    #pragma unroll
    for (int q = 0; q < 4; q++) {
        float d0 = an0[q] - pn0[q];
        float d1 = an1[q] - pn1[q];
        d20 = fmaf(d0, d0, d20);
        d21 = fmaf(d1, d1, d21);
    }
    #pragma unroll
    for (int o = 16; o > 0; o >>= 1) {
        d20 += __shfl_xor_sync(0xffffffffu, d20, o);
        d21 += __shfl_xor_sync(0xffffffffu, d21, o);
    }

    if (lane == 0) {
        g_posd[r0]        = d20;
        g_posd[r0 + 1]    = d21;
        g_lab[r0]         = labels[r0];
        g_lab[r0 + 1]     = labels[r0 + 1];
        g_maxbits[r0]     = 0;
        g_maxbits[r0 + 1] = 0;
    }
}

// ---------------------------------------------------------------------------
// Kernel 2: symmetric max-gram, single-term fp16 mma.sync, 512 threads.
// Warp grid 4(M) x 4(N): warp tile 32 rows x 32 cols. ldmatrix fragments.
// SMEM: [A][B0][B1], rows padded to 272 B. 148 CTAs (1/SM); CTA b handles
// 14 + (b<8) consecutive triangular tiles -> near-perfect balance.
// ---------------------------------------------------------------------------
__global__ void __launch_bounds__(512, 1) maxgram_sym() {
    extern __shared__ char dsm[];
    __shared__ int labJ[2][128];

    const int tid  = threadIdx.x;
    const int lane = tid & 31;
    const int wid  = tid >> 5;
    const int wm   = wid & 3;         // M quarter (32 rows)
    const int wn   = wid >> 2;        // N quarter (32 cols)
    const int g    = lane >> 2;
    const int q    = lane & 3;

    const uint32_t smb = smem_u32(dsm);

    // ldmatrix per-lane base byte offsets within a tile
    const uint32_t aoff = (uint32_t)(wm * 32 + (lane & 15)) * STRB + (uint32_t)(lane >> 4) * 16;
    const uint32_t boff = (uint32_t)(wn * 32 + ((lane >> 4) << 3) + (lane & 7)) * STRB
                        + (uint32_t)((lane >> 3) & 1) * 16;

    // tile range for this CTA (remainder spread over first 8 CTAs)
    const int bid  = blockIdx.x;
    const int L    = bid * 14 + min(bid, 8);
    const int MYT  = 14 + (bid < 8 ? 1 : 0);

    // decode starting tile (triangular row-major)
    int ti = 0, base = 0;
    while (base + (NTILE - ti) <= L) { base += NTILE - ti; ti++; }
    int tj = ti + (L - base);

    auto loadA = [&](int t) {
        const int i0 = t * 128;
        for (int idx = tid; idx < 2048; idx += 512) {
            int r = idx >> 4, c = idx & 15;
            cpasync16(smb + r * STRB + c * 16,
                      g_af16 + (size_t)(i0 + r) * ND + c * 8);
        }
    };
    auto loadB = [&](int t, int buf) {
        const int j0 = t * 128;
        uint32_t bb = smb + (1 + buf) * TILE_BYTES;
        for (int idx = tid; idx < 2048; idx += 512) {
            int r = idx >> 4, c = idx & 15;
            cpasync16(bb + r * STRB + c * 16,
                      g_af16 + (size_t)(j0 + r) * ND + c * 8);
        }
        if (tid < 128) labJ[buf][tid] = g_lab[j0 + tid];
    };

    int lr[2][2];
    auto loadLr = [&](int t) {
        #pragma unroll
        for (int mt = 0; mt < 2; mt++) {
            int r = t * 128 + wm * 32 + mt * 16 + g;
            lr[mt][0] = g_lab[r];
            lr[mt][1] = g_lab[r + 8];
        }
    };

    float mx[2][2];
    #pragma unroll
    for (int mt = 0; mt < 2; mt++) { mx[mt][0] = -3.0f; mx[mt][1] = -3.0f; }

    auto flushRows = [&](int t) {
        #pragma unroll
        for (int mt = 0; mt < 2; mt++)
            #pragma unroll
            for (int r = 0; r < 2; r++) {
                float v = mx[mt][r];
                v = fmaxf(v, __shfl_xor_sync(0xffffffffu, v, 1));
                v = fmaxf(v, __shfl_xor_sync(0xffffffffu, v, 2));
                if (q == 0)
                    atomicMax(&g_maxbits[t * 128 + wm * 32 + mt * 16 + g + r * 8],
                              __float_as_int(fmaxf(v + 2.0f, 0.0f)));
                mx[mt][r] = -3.0f;
            }
    };

    // prologue
    loadA(ti);
    loadB(tj, 0);
    asm volatile("cp.async.commit_group;");
    loadLr(ti);

    for (int n = 0; n < MYT; n++) {
        const int buf = n & 1;

        int ti_n = ti, tj_n = tj + 1;
        if (tj_n == NTILE) { ti_n = ti + 1; tj_n = ti_n; }

        asm volatile("cp.async.wait_group 0;" ::: "memory");
        __syncthreads();

        if (n + 1 < MYT) {
            loadB(tj_n, buf ^ 1);
            asm volatile("cp.async.commit_group;");
        }

        // ---- compute tile (ti, tj): single fp16 term ----
        const uint32_t Abase = smb + aoff;
        const uint32_t Bbase = smb + (1 + buf) * TILE_BYTES + boff;

        float acc[2][4][4];
        #pragma unroll
        for (int mt = 0; mt < 2; mt++)
            #pragma unroll
            for (int nt = 0; nt < 4; nt++)
                #pragma unroll
                for (int e = 0; e < 4; e++) acc[mt][nt][e] = 0.0f;

        #pragma unroll
        for (int ks = 0; ks < 8; ks++) {
            const uint32_t ko = ks * 32;

            uint32_t a[2][4], b[4][2];
            #pragma unroll
            for (int mt = 0; mt < 2; mt++)
                ldsm4(a[mt], Abase + mt * (16 * STRB) + ko);
            #pragma unroll
            for (int p = 0; p < 2; p++) {
                uint32_t rb[4];
                ldsm4(rb, Bbase + p * (16 * STRB) + ko);
                b[2*p][0] = rb[0]; b[2*p][1] = rb[1];
                b[2*p+1][0] = rb[2]; b[2*p+1][1] = rb[3];
            }
            #pragma unroll
            for (int mt = 0; mt < 2; mt++)
                #pragma unroll
                for (int nt = 0; nt < 4; nt++)
                    mma16816(acc[mt][nt], a[mt], b[nt]);
        }

        // ---- epilogue: mask, row-max, column-max ----
        float cmax[4][2];
        #pragma unroll
        for (int nt = 0; nt < 4; nt++) { cmax[nt][0] = -3.0f; cmax[nt][1] = -3.0f; }

        #pragma unroll
        for (int nt = 0; nt < 4; nt++) {
            int c0 = wn * 32 + nt * 8 + q * 2;
            int l0 = labJ[buf][c0], l1 = labJ[buf][c0 + 1];
            #pragma unroll
            for (int mt = 0; mt < 2; mt++) {
                float v0 = (l0 == lr[mt][0]) ? -3.0f : acc[mt][nt][0];
                float v1 = (l1 == lr[mt][0]) ? -3.0f : acc[mt][nt][1];
                float v2 = (l0 == lr[mt][1]) ? -3.0f : acc[mt][nt][2];
                float v3 = (l1 == lr[mt][1]) ? -3.0f : acc[mt][nt][3];
                mx[mt][0] = fmaxf(mx[mt][0], fmaxf(v0, v1));
                mx[mt][1] = fmaxf(mx[mt][1], fmaxf(v2, v3));
                cmax[nt][0] = fmaxf(cmax[nt][0], fmaxf(v0, v2));
                cmax[nt][1] = fmaxf(cmax[nt][1], fmaxf(v1, v3));
            }
        }

        if (ti != tj) {
            #pragma unroll
            for (int nt = 0; nt < 4; nt++)
                #pragma unroll
                for (int e = 0; e < 2; e++) {
                    float v = cmax[nt][e];
                    v = fmaxf(v, __shfl_xor_sync(0xffffffffu, v, 4));
                    v = fmaxf(v, __shfl_xor_sync(0xffffffffu, v, 8));
                    v = fmaxf(v, __shfl_xor_sync(0xffffffffu, v, 16));
                    if (g == 0)
                        atomicMax(&g_maxbits[tj * 128 + wn * 32 + nt * 8 + q * 2 + e],
                                  __float_as_int(fmaxf(v + 2.0f, 0.0f)));
                }
        }

        if (n + 1 < MYT) {
            if (ti_n != ti) {
                flushRows(ti);
                __syncthreads();          // all warps done reading A
                loadA(ti_n);
                asm volatile("cp.async.commit_group;");
                loadLr(ti_n);
            }
            ti = ti_n; tj = tj_n;
        }
    }
    flushRows(ti);
}

// ---------------------------------------------------------------------------
// Kernel 3: final loss reduction.
// ---------------------------------------------------------------------------
__global__ void finalize_kernel(float* __restrict__ out) {
    __shared__ float red[256];
    float s = 0.0f;
    for (int i = threadIdx.x; i < NB; i += 256) {
        float gmax = __int_as_float(g_maxbits[i]) - 2.0f;
        float neg  = fmaxf(2.0f - 2.0f * gmax, 0.0f);
        float l    = g_posd[i] - neg + MARGIN;
        s += fmaxf(l, 0.0f);
    }
    red[threadIdx.x] = s;
    __syncthreads();
    #pragma unroll
    for (int stride = 128; stride > 0; stride >>= 1) {
        if (threadIdx.x < stride) red[threadIdx.x] += red[threadIdx.x + stride];
        __syncthreads();
    }
    if (threadIdx.x == 0) out[0] = red[0] / (float)NB;
}

extern "C" void kernel_launch(void* const* d_in, const int* in_sizes, int n_in,
                              void* d_out, int out_size) {
    const float* anchor   = (const float*)d_in[0];
    const float* positive = (const float*)d_in[1];
    const int*   labels   = (const int*)d_in[2];   // JAX x64 disabled: int64 -> int32
    float*       out      = (float*)d_out;

    prep_kernel<<<NB / 16, 256>>>(anchor, positive, labels);   // 2 rows per warp

    const int smem = 3 * TILE_BYTES;   // 104448 B
    cudaFuncSetAttribute(maxgram_sym, cudaFuncAttributeMaxDynamicSharedMemorySize, smem);
    maxgram_sym<<<GRID, 512, smem>>>();

    finalize_kernel<<<1, 256>>>(out);
}

// round 9
// speedup vs baseline: 1.2465x; 1.2465x over previous
#include <cuda_runtime.h>
#include <cuda_fp16.h>
#include <cstdint>

// Problem constants (fixed: B=8192, D=128)
#define NB 8192
#define ND 128
#define NTILE 64                    // 8192 / 128 tile rows
#define GRID 296                    // exactly 2 CTAs per SM
#define MARGIN 0.5f
#define STRB 272                    // padded row stride in bytes -> conflict-free ldmatrix
#define TILE_BYTES (128 * STRB)     // 34816 per 128x128 fp16 tile

// Device scratch (no allocation allowed)
__device__ __align__(16) __half g_af16[NB * ND];
__device__ float g_posd[NB];
__device__ int   g_lab[NB];
__device__ int   g_maxbits[NB];

// ---------------------------------------------------------------------------
// helpers
// ---------------------------------------------------------------------------
__device__ __forceinline__ uint32_t smem_u32(const void* p) {
    uint32_t a;
    asm("{ .reg .u64 t; cvta.to.shared.u64 t, %1; cvt.u32.u64 %0, t; }" : "=r"(a) : "l"(p));
    return a;
}
__device__ __forceinline__ void cpasync16(uint32_t dst, const void* src) {
    asm volatile("cp.async.cg.shared.global [%0], [%1], 16;" :: "r"(dst), "l"(src));
}
__device__ __forceinline__ void mma16816(float* c, const uint32_t* a, const uint32_t* b) {
    asm volatile(
        "mma.sync.aligned.m16n8k16.row.col.f32.f16.f16.f32 "
        "{%0,%1,%2,%3}, {%4,%5,%6,%7}, {%8,%9}, {%0,%1,%2,%3};"
        : "+f"(c[0]), "+f"(c[1]), "+f"(c[2]), "+f"(c[3])
        : "r"(a[0]), "r"(a[1]), "r"(a[2]), "r"(a[3]), "r"(b[0]), "r"(b[1]));
}
__device__ __forceinline__ void ldsm4(uint32_t* r, uint32_t addr) {
    asm volatile("ldmatrix.sync.aligned.m8n8.x4.shared.b16 {%0,%1,%2,%3}, [%4];"
        : "=r"(r[0]), "=r"(r[1]), "=r"(r[2]), "=r"(r[3]) : "r"(addr));
}

// ---------------------------------------------------------------------------
// Kernel 1: normalize anchors -> fp16; pos_dist; labels; init max.
// Two rows per warp.
// ---------------------------------------------------------------------------
__global__ void prep_kernel(const float* __restrict__ anchor,
                            const float* __restrict__ positive,
                            const int* __restrict__ labels) {
    int pair = (blockIdx.x * blockDim.x + threadIdx.x) >> 5;
    int lane = threadIdx.x & 31;
    int r0 = pair * 2;
    if (r0 >= NB) return;

    const float4* a0 = reinterpret_cast<const float4*>(anchor   + (size_t)r0 * ND);
    const float4* a1 = reinterpret_cast<const float4*>(anchor   + (size_t)(r0 + 1) * ND);
    const float4* p0 = reinterpret_cast<const float4*>(positive + (size_t)r0 * ND);
    const float4* p1 = reinterpret_cast<const float4*>(positive + (size_t)(r0 + 1) * ND);
    float4 av0 = a0[lane], av1 = a1[lane], pv0 = p0[lane], pv1 = p1[lane];

    float sa0 = av0.x*av0.x + av0.y*av0.y + av0.z*av0.z + av0.w*av0.w;
    float sa1 = av1.x*av1.x + av1.y*av1.y + av1.z*av1.z + av1.w*av1.w;
    float sp0 = pv0.x*pv0.x + pv0.y*pv0.y + pv0.z*pv0.z + pv0.w*pv0.w;
    float sp1 = pv1.x*pv1.x + pv1.y*pv1.y + pv1.z*pv1.z + pv1.w*pv1.w;
    #pragma unroll
    for (int o = 16; o > 0; o >>= 1) {
        sa0 += __shfl_xor_sync(0xffffffffu, sa0, o);
        sa1 += __shfl_xor_sync(0xffffffffu, sa1, o);
        sp0 += __shfl_xor_sync(0xffffffffu, sp0, o);
        sp1 += __shfl_xor_sync(0xffffffffu, sp1, o);
    }
    float ia0 = 1.0f / fmaxf(sqrtf(sa0), 1e-12f);
    float ia1 = 1.0f / fmaxf(sqrtf(sa1), 1e-12f);
    float ip0 = 1.0f / fmaxf(sqrtf(sp0), 1e-12f);
    float ip1 = 1.0f / fmaxf(sqrtf(sp1), 1e-12f);

    float an0[4] = {av0.x*ia0, av0.y*ia0, av0.z*ia0, av0.w*ia0};
    float an1[4] = {av1.x*ia1, av1.y*ia1, av1.z*ia1, av1.w*ia1};
    float pn0[4] = {pv0.x*ip0, pv0.y*ip0, pv0.z*ip0, pv0.w*ip0};
    float pn1[4] = {pv1.x*ip1, pv1.y*ip1, pv1.z*ip1, pv1.w*ip1};

    __half2 h0a; h0a.x = __float2half_rn(an0[0]); h0a.y = __float2half_rn(an0[1]);
    __half2 h0b; h0b.x = __float2half_rn(an0[2]); h0b.y = __float2half_rn(an0[3]);
    __half2 h1a; h1a.x = __float2half_rn(an1[0]); h1a.y = __float2half_rn(an1[1]);
    __half2 h1b; h1b.x = __float2half_rn(an1[2]); h1b.y = __float2half_rn(an1[3]);
    size_t b0 = (size_t)r0 * ND + lane * 4;
    reinterpret_cast<__half2*>(g_af16 + b0)[0] = h0a;
    reinterpret_cast<__half2*>(g_af16 + b0)[1] = h0b;
    reinterpret_cast<__half2*>(g_af16 + b0 + ND)[0] = h1a;
    reinterpret_cast<__half2*>(g_af16 + b0 + ND)[1] = h1b;

    float d20 = 0.0f, d21 = 0.0f;
    #pragma unroll
    for (int q = 0; q < 4; q++) {
        float d0 = an0[q] - pn0[q];
        float d1 = an1[q] - pn1[q];
        d20 = fmaf(d0, d0, d20);
        d21 = fmaf(d1, d1, d21);
    }
    #pragma unroll
    for (int o = 16; o > 0; o >>= 1) {
        d20 += __shfl_xor_sync(0xffffffffu, d20, o);
        d21 += __shfl_xor_sync(0xffffffffu, d21, o);
    }

    if (lane == 0) {
        g_posd[r0]        = d20;
        g_posd[r0 + 1]    = d21;
        g_lab[r0]         = labels[r0];
        g_lab[r0 + 1]     = labels[r0 + 1];
        g_maxbits[r0]     = 0;
        g_maxbits[r0 + 1] = 0;
    }
}

// ---------------------------------------------------------------------------
// Kernel 2: symmetric max-gram, single-term fp16 mma.sync.
// 8 warps, 2(M) x 4(N): warp tile 64 rows x 32 cols. ldmatrix fragments.
// SMEM: [A][B0][B1], rows padded to 272 B. 296 CTAs (2/SM, occupancy 2);
// CTA b handles 7 + (b<8) consecutive triangular tiles -> SM load 14-15.
// ---------------------------------------------------------------------------
__global__ void __launch_bounds__(256, 2) maxgram_sym() {
    extern __shared__ char dsm[];
    __shared__ int labJ[2][128];

    const int tid  = threadIdx.x;
    const int lane = tid & 31;
    const int wid  = tid >> 5;
    const int wm   = wid & 1;         // M half (64 rows)
    const int wn   = wid >> 1;        // N quarter (32 cols)
    const int g    = lane >> 2;
    const int q    = lane & 3;

    const uint32_t smb = smem_u32(dsm);

    // ldmatrix per-lane base byte offsets within a tile
    const uint32_t aoff = (uint32_t)(wm * 64 + (lane & 15)) * STRB + (uint32_t)(lane >> 4) * 16;
    const uint32_t boff = (uint32_t)(wn * 32 + ((lane >> 4) << 3) + (lane & 7)) * STRB
                        + (uint32_t)((lane >> 3) & 1) * 16;

    // tile range for this CTA (remainder on first 8 CTAs; bid & bid+148 share an SM)
    const int bid = blockIdx.x;
    const int L   = bid * 7 + min(bid, 8);
    const int MYT = 7 + (bid < 8 ? 1 : 0);

    // decode starting tile (triangular row-major)
    int ti = 0, base = 0;
    while (base + (NTILE - ti) <= L) { base += NTILE - ti; ti++; }
    int tj = ti + (L - base);

    auto loadA = [&](int t) {
        const int i0 = t * 128;
        for (int idx = tid; idx < 2048; idx += 256) {
            int r = idx >> 4, c = idx & 15;
            cpasync16(smb + r * STRB + c * 16,
                      g_af16 + (size_t)(i0 + r) * ND + c * 8);
        }
    };
    auto loadB = [&](int t, int buf) {
        const int j0 = t * 128;
        uint32_t bb = smb + (1 + buf) * TILE_BYTES;
        for (int idx = tid; idx < 2048; idx += 256) {
            int r = idx >> 4, c = idx & 15;
            cpasync16(bb + r * STRB + c * 16,
                      g_af16 + (size_t)(j0 + r) * ND + c * 8);
        }
        if (tid < 128) labJ[buf][tid] = g_lab[j0 + tid];
    };

    int lr[4][2];
    auto loadLr = [&](int t) {
        #pragma unroll
        for (int mt = 0; mt < 4; mt++) {
            int r = t * 128 + wm * 64 + mt * 16 + g;
            lr[mt][0] = g_lab[r];
            lr[mt][1] = g_lab[r + 8];
        }
    };

    float mx[4][2];
    #pragma unroll
    for (int mt = 0; mt < 4; mt++) { mx[mt][0] = -3.0f; mx[mt][1] = -3.0f; }

    auto flushRows = [&](int t) {
        #pragma unroll
        for (int mt = 0; mt < 4; mt++)
            #pragma unroll
            for (int r = 0; r < 2; r++) {
                float v = mx[mt][r];
                v = fmaxf(v, __shfl_xor_sync(0xffffffffu, v, 1));
                v = fmaxf(v, __shfl_xor_sync(0xffffffffu, v, 2));
                if (q == 0)
                    atomicMax(&g_maxbits[t * 128 + wm * 64 + mt * 16 + g + r * 8],
                              __float_as_int(fmaxf(v + 2.0f, 0.0f)));
                mx[mt][r] = -3.0f;
            }
    };

    // prologue
    loadA(ti);
    loadB(tj, 0);
    asm volatile("cp.async.commit_group;");
    loadLr(ti);

    for (int n = 0; n < MYT; n++) {
        const int buf = n & 1;

        int ti_n = ti, tj_n = tj + 1;
        if (tj_n == NTILE) { ti_n = ti + 1; tj_n = ti_n; }

        asm volatile("cp.async.wait_group 0;" ::: "memory");
        __syncthreads();

        if (n + 1 < MYT) {
            loadB(tj_n, buf ^ 1);
            asm volatile("cp.async.commit_group;");
        }

        // ---- compute tile (ti, tj): single fp16 term ----
        const uint32_t Abase = smb + aoff;
        const uint32_t Bbase = smb + (1 + buf) * TILE_BYTES + boff;

        float acc[4][4][4];
        #pragma unroll
        for (int mt = 0; mt < 4; mt++)
            #pragma unroll
            for (int nt = 0; nt < 4; nt++)
                #pragma unroll
                for (int e = 0; e < 4; e++) acc[mt][nt][e] = 0.0f;

        #pragma unroll
        for (int ks = 0; ks < 8; ks++) {
            const uint32_t ko = ks * 32;

            uint32_t a[4][4], b[4][2];
            #pragma unroll
            for (int mt = 0; mt < 4; mt++)
                ldsm4(a[mt], Abase + mt * (16 * STRB) + ko);
            #pragma unroll
            for (int p = 0; p < 2; p++) {
                uint32_t rb[4];
                ldsm4(rb, Bbase + p * (16 * STRB) + ko);
                b[2*p][0] = rb[0]; b[2*p][1] = rb[1];
                b[2*p+1][0] = rb[2]; b[2*p+1][1] = rb[3];
            }
            #pragma unroll
            for (int mt = 0; mt < 4; mt++)
                #pragma unroll
                for (int nt = 0; nt < 4; nt++)
                    mma16816(acc[mt][nt], a[mt], b[nt]);
        }

        // ---- epilogue: mask, row-max, column-max ----
        float cmax[4][2];
        #pragma unroll
        for (int nt = 0; nt < 4; nt++) { cmax[nt][0] = -3.0f; cmax[nt][1] = -3.0f; }

        #pragma unroll
        for (int nt = 0; nt < 4; nt++) {
            int c0 = wn * 32 + nt * 8 + q * 2;
            int l0 = labJ[buf][c0], l1 = labJ[buf][c0 + 1];
            #pragma unroll
            for (int mt = 0; mt < 4; mt++) {
                float v0 = (l0 == lr[mt][0]) ? -3.0f : acc[mt][nt][0];
                float v1 = (l1 == lr[mt][0]) ? -3.0f : acc[mt][nt][1];
                float v2 = (l0 == lr[mt][1]) ? -3.0f : acc[mt][nt][2];
                float v3 = (l1 == lr[mt][1]) ? -3.0f : acc[mt][nt][3];
                mx[mt][0] = fmaxf(mx[mt][0], fmaxf(v0, v1));
                mx[mt][1] = fmaxf(mx[mt][1], fmaxf(v2, v3));
                cmax[nt][0] = fmaxf(cmax[nt][0], fmaxf(v0, v2));
                cmax[nt][1] = fmaxf(cmax[nt][1], fmaxf(v1, v3));
            }
        }

        if (ti != tj) {
            #pragma unroll
            for (int nt = 0; nt < 4; nt++)
                #pragma unroll
                for (int e = 0; e < 2; e++) {
                    float v = cmax[nt][e];
                    v = fmaxf(v, __shfl_xor_sync(0xffffffffu, v, 4));
                    v = fmaxf(v, __shfl_xor_sync(0xffffffffu, v, 8));
                    v = fmaxf(v, __shfl_xor_sync(0xffffffffu, v, 16));
                    if (g == 0)
                        atomicMax(&g_maxbits[tj * 128 + wn * 32 + nt * 8 + q * 2 + e],
                                  __float_as_int(fmaxf(v + 2.0f, 0.0f)));
                }
        }

        if (n + 1 < MYT) {
            if (ti_n != ti) {
                flushRows(ti);
                __syncthreads();          // all warps done reading A
                loadA(ti_n);
                asm volatile("cp.async.commit_group;");
                loadLr(ti_n);
            }
            ti = ti_n; tj = tj_n;
        }
    }
    flushRows(ti);
}

// ---------------------------------------------------------------------------
// Kernel 3: final loss reduction.
// ---------------------------------------------------------------------------
__global__ void finalize_kernel(float* __restrict__ out) {
    __shared__ float red[256];
    float s = 0.0f;
    for (int i = threadIdx.x; i < NB; i += 256) {
        float gmax = __int_as_float(g_maxbits[i]) - 2.0f;
        float neg  = fmaxf(2.0f - 2.0f * gmax, 0.0f);
        float l    = g_posd[i] - neg + MARGIN;
        s += fmaxf(l, 0.0f);
    }
    red[threadIdx.x] = s;
    __syncthreads();
    #pragma unroll
    for (int stride = 128; stride > 0; stride >>= 1) {
        if (threadIdx.x < stride) red[threadIdx.x] += red[threadIdx.x + stride];
        __syncthreads();
    }
    if (threadIdx.x == 0) out[0] = red[0] / (float)NB;
}

extern "C" void kernel_launch(void* const* d_in, const int* in_sizes, int n_in,
                              void* d_out, int out_size) {
    const float* anchor   = (const float*)d_in[0];
    const float* positive = (const float*)d_in[1];
    const int*   labels   = (const int*)d_in[2];   // JAX x64 disabled: int64 -> int32
    float*       out      = (float*)d_out;

    prep_kernel<<<NB / 16, 256>>>(anchor, positive, labels);

    const int smem = 3 * TILE_BYTES;   // 104448 B -> 2 CTAs/SM
    cudaFuncSetAttribute(maxgram_sym, cudaFuncAttributeMaxDynamicSharedMemorySize, smem);
    maxgram_sym<<<GRID, 256, smem>>>();

    finalize_kernel<<<1, 256>>>(out);
}

// round 10
// speedup vs baseline: 1.2533x; 1.0054x over previous
#include <cuda_runtime.h>
#include <cuda_fp16.h>
#include <cstdint>

// Problem constants (fixed: B=8192, D=128)
#define NB 8192
#define ND 128
#define NTILE 64                    // 8192 / 128 tile rows
#define GRID 296                    // exactly 2 CTAs per SM
#define MARGIN 0.5f
#define STRB 272                    // padded row stride in bytes -> conflict-free ldmatrix
#define TILE_BYTES (128 * STRB)     // 34816 per 128x128 fp16 tile

// Device scratch (no allocation allowed)
__device__ __align__(16) __half g_af16[NB * ND];
__device__ float g_posd[NB];
__device__ int   g_lab[NB];
__device__ int   g_maxbits[NB];
__device__ int   g_done;

// ---------------------------------------------------------------------------
// helpers
// ---------------------------------------------------------------------------
__device__ __forceinline__ uint32_t smem_u32(const void* p) {
    uint32_t a;
    asm("{ .reg .u64 t; cvta.to.shared.u64 t, %1; cvt.u32.u64 %0, t; }" : "=r"(a) : "l"(p));
    return a;
}
__device__ __forceinline__ void cpasync16(uint32_t dst, const void* src) {
    asm volatile("cp.async.cg.shared.global [%0], [%1], 16;" :: "r"(dst), "l"(src));
}
__device__ __forceinline__ void mma16816(float* c, const uint32_t* a, const uint32_t* b) {
    asm volatile(
        "mma.sync.aligned.m16n8k16.row.col.f32.f16.f16.f32 "
        "{%0,%1,%2,%3}, {%4,%5,%6,%7}, {%8,%9}, {%0,%1,%2,%3};"
        : "+f"(c[0]), "+f"(c[1]), "+f"(c[2]), "+f"(c[3])
        : "r"(a[0]), "r"(a[1]), "r"(a[2]), "r"(a[3]), "r"(b[0]), "r"(b[1]));
}
__device__ __forceinline__ void ldsm4(uint32_t* r, uint32_t addr) {
    asm volatile("ldmatrix.sync.aligned.m8n8.x4.shared.b16 {%0,%1,%2,%3}, [%4];"
        : "=r"(r[0]), "=r"(r[1]), "=r"(r[2]), "=r"(r[3]) : "r"(addr));
}

// ---------------------------------------------------------------------------
// Kernel 1: normalize anchors -> fp16; pos_dist; labels; init max.
// FOUR rows per warp: 8 front-batched LDG.128 -> MLP 8 (latency-bound kernel).
// ---------------------------------------------------------------------------
__global__ void prep_kernel(const float* __restrict__ anchor,
                            const float* __restrict__ positive,
                            const int* __restrict__ labels) {
    int gw   = (blockIdx.x * blockDim.x + threadIdx.x) >> 5;
    int lane = threadIdx.x & 31;
    int r0 = gw * 4;
    if (r0 >= NB) return;
    if (gw == 0 && lane == 0) g_done = 0;   // reset fused-finalize counter each call

    float4 av[4], pv[4];
    #pragma unroll
    for (int k = 0; k < 4; k++) {
        av[k] = reinterpret_cast<const float4*>(anchor   + (size_t)(r0 + k) * ND)[lane];
        pv[k] = reinterpret_cast<const float4*>(positive + (size_t)(r0 + k) * ND)[lane];
    }

    float sa[4], sp[4];
    #pragma unroll
    for (int k = 0; k < 4; k++) {
        sa[k] = av[k].x*av[k].x + av[k].y*av[k].y + av[k].z*av[k].z + av[k].w*av[k].w;
        sp[k] = pv[k].x*pv[k].x + pv[k].y*pv[k].y + pv[k].z*pv[k].z + pv[k].w*pv[k].w;
    }
    #pragma unroll
    for (int o = 16; o > 0; o >>= 1)
        #pragma unroll
        for (int k = 0; k < 4; k++) {
            sa[k] += __shfl_xor_sync(0xffffffffu, sa[k], o);
            sp[k] += __shfl_xor_sync(0xffffffffu, sp[k], o);
        }

    float d2[4];
    #pragma unroll
    for (int k = 0; k < 4; k++) {
        float ia = 1.0f / fmaxf(sqrtf(sa[k]), 1e-12f);
        float ip = 1.0f / fmaxf(sqrtf(sp[k]), 1e-12f);
        float an[4] = {av[k].x*ia, av[k].y*ia, av[k].z*ia, av[k].w*ia};
        float pn[4] = {pv[k].x*ip, pv[k].y*ip, pv[k].z*ip, pv[k].w*ip};

        __half2 ha; ha.x = __float2half_rn(an[0]); ha.y = __float2half_rn(an[1]);
        __half2 hb; hb.x = __float2half_rn(an[2]); hb.y = __float2half_rn(an[3]);
        size_t base = (size_t)(r0 + k) * ND + lane * 4;
        reinterpret_cast<__half2*>(g_af16 + base)[0] = ha;
        reinterpret_cast<__half2*>(g_af16 + base)[1] = hb;

        float s = 0.0f;
        #pragma unroll
        for (int q = 0; q < 4; q++) {
            float d = an[q] - pn[q];
            s = fmaf(d, d, s);
        }
        d2[k] = s;
    }
    #pragma unroll
    for (int o = 16; o > 0; o >>= 1)
        #pragma unroll
        for (int k = 0; k < 4; k++)
            d2[k] += __shfl_xor_sync(0xffffffffu, d2[k], o);

    if (lane < 4) {
        g_posd[r0 + lane]    = d2[lane];
        g_lab[r0 + lane]     = labels[r0 + lane];
        g_maxbits[r0 + lane] = 0;
    }
}

// ---------------------------------------------------------------------------
// Kernel 2: symmetric max-gram, single-term fp16 mma.sync, fused finalize.
// 8 warps, 2(M) x 4(N): warp tile 64 rows x 32 cols. 296 CTAs (2/SM);
// CTA b handles 7 + (b<8) triangular tiles. Last CTA to finish reduces loss.
// ---------------------------------------------------------------------------
__global__ void __launch_bounds__(256, 2) maxgram_sym(float* __restrict__ out) {
    extern __shared__ char dsm[];
    __shared__ int labJ[2][128];
    __shared__ int s_last;
    __shared__ float red[256];

    const int tid  = threadIdx.x;
    const int lane = tid & 31;
    const int wid  = tid >> 5;
    const int wm   = wid & 1;         // M half (64 rows)
    const int wn   = wid >> 1;        // N quarter (32 cols)
    const int g    = lane >> 2;
    const int q    = lane & 3;

    const uint32_t smb = smem_u32(dsm);

    // ldmatrix per-lane base byte offsets within a tile
    const uint32_t aoff = (uint32_t)(wm * 64 + (lane & 15)) * STRB + (uint32_t)(lane >> 4) * 16;
    const uint32_t boff = (uint32_t)(wn * 32 + ((lane >> 4) << 3) + (lane & 7)) * STRB
                        + (uint32_t)((lane >> 3) & 1) * 16;

    // tile range for this CTA (remainder on first 8 CTAs; bid & bid+148 share an SM)
    const int bid = blockIdx.x;
    const int L   = bid * 7 + min(bid, 8);
    const int MYT = 7 + (bid < 8 ? 1 : 0);

    // decode starting tile (triangular row-major)
    int ti = 0, base = 0;
    while (base + (NTILE - ti) <= L) { base += NTILE - ti; ti++; }
    int tj = ti + (L - base);

    auto loadA = [&](int t) {
        const int i0 = t * 128;
        for (int idx = tid; idx < 2048; idx += 256) {
            int r = idx >> 4, c = idx & 15;
            cpasync16(smb + r * STRB + c * 16,
                      g_af16 + (size_t)(i0 + r) * ND + c * 8);
        }
    };
    auto loadB = [&](int t, int buf) {
        const int j0 = t * 128;
        uint32_t bb = smb + (1 + buf) * TILE_BYTES;
        for (int idx = tid; idx < 2048; idx += 256) {
            int r = idx >> 4, c = idx & 15;
            cpasync16(bb + r * STRB + c * 16,
                      g_af16 + (size_t)(j0 + r) * ND + c * 8);
        }
        if (tid < 128) labJ[buf][tid] = g_lab[j0 + tid];
    };

    int lr[4][2];
    auto loadLr = [&](int t) {
        #pragma unroll
        for (int mt = 0; mt < 4; mt++) {
            int r = t * 128 + wm * 64 + mt * 16 + g;
            lr[mt][0] = g_lab[r];
            lr[mt][1] = g_lab[r + 8];
        }
    };

    float mx[4][2];
    #pragma unroll
    for (int mt = 0; mt < 4; mt++) { mx[mt][0] = -3.0f; mx[mt][1] = -3.0f; }

    auto flushRows = [&](int t) {
        #pragma unroll
        for (int mt = 0; mt < 4; mt++)
            #pragma unroll
            for (int r = 0; r < 2; r++) {
                float v = mx[mt][r];
                v = fmaxf(v, __shfl_xor_sync(0xffffffffu, v, 1));
                v = fmaxf(v, __shfl_xor_sync(0xffffffffu, v, 2));
                if (q == 0)
                    atomicMax(&g_maxbits[t * 128 + wm * 64 + mt * 16 + g + r * 8],
                              __float_as_int(fmaxf(v + 2.0f, 0.0f)));
                mx[mt][r] = -3.0f;
            }
    };

    // prologue
    loadA(ti);
    loadB(tj, 0);
    asm volatile("cp.async.commit_group;");
    loadLr(ti);

    for (int n = 0; n < MYT; n++) {
        const int buf = n & 1;

        int ti_n = ti, tj_n = tj + 1;
        if (tj_n == NTILE) { ti_n = ti + 1; tj_n = ti_n; }

        asm volatile("cp.async.wait_group 0;" ::: "memory");
        __syncthreads();

        if (n + 1 < MYT) {
            loadB(tj_n, buf ^ 1);
            asm volatile("cp.async.commit_group;");
        }

        // ---- compute tile (ti, tj): single fp16 term ----
        const uint32_t Abase = smb + aoff;
        const uint32_t Bbase = smb + (1 + buf) * TILE_BYTES + boff;

        float acc[4][4][4];
        #pragma unroll
        for (int mt = 0; mt < 4; mt++)
            #pragma unroll
            for (int nt = 0; nt < 4; nt++)
                #pragma unroll
                for (int e = 0; e < 4; e++) acc[mt][nt][e] = 0.0f;

        #pragma unroll
        for (int ks = 0; ks < 8; ks++) {
            const uint32_t ko = ks * 32;

            uint32_t a[4][4], b[4][2];
            #pragma unroll
            for (int mt = 0; mt < 4; mt++)
                ldsm4(a[mt], Abase + mt * (16 * STRB) + ko);
            #pragma unroll
            for (int p = 0; p < 2; p++) {
                uint32_t rb[4];
                ldsm4(rb, Bbase + p * (16 * STRB) + ko);
                b[2*p][0] = rb[0]; b[2*p][1] = rb[1];
                b[2*p+1][0] = rb[2]; b[2*p+1][1] = rb[3];
            }
            #pragma unroll
            for (int mt = 0; mt < 4; mt++)
                #pragma unroll
                for (int nt = 0; nt < 4; nt++)
                    mma16816(acc[mt][nt], a[mt], b[nt]);
        }

        // ---- epilogue: mask, row-max, column-max ----
        float cmax[4][2];
        #pragma unroll
        for (int nt = 0; nt < 4; nt++) { cmax[nt][0] = -3.0f; cmax[nt][1] = -3.0f; }

        #pragma unroll
        for (int nt = 0; nt < 4; nt++) {
            int c0 = wn * 32 + nt * 8 + q * 2;
            int l0 = labJ[buf][c0], l1 = labJ[buf][c0 + 1];
            #pragma unroll
            for (int mt = 0; mt < 4; mt++) {
                float v0 = (l0 == lr[mt][0]) ? -3.0f : acc[mt][nt][0];
                float v1 = (l1 == lr[mt][0]) ? -3.0f : acc[mt][nt][1];
                float v2 = (l0 == lr[mt][1]) ? -3.0f : acc[mt][nt][2];
                float v3 = (l1 == lr[mt][1]) ? -3.0f : acc[mt][nt][3];
                mx[mt][0] = fmaxf(mx[mt][0], fmaxf(v0, v1));
                mx[mt][1] = fmaxf(mx[mt][1], fmaxf(v2, v3));
                cmax[nt][0] = fmaxf(cmax[nt][0], fmaxf(v0, v2));
                cmax[nt][1] = fmaxf(cmax[nt][1], fmaxf(v1, v3));
            }
        }

        if (ti != tj) {
            #pragma unroll
            for (int nt = 0; nt < 4; nt++)
                #pragma unroll
                for (int e = 0; e < 2; e++) {
                    float v = cmax[nt][e];
                    v = fmaxf(v, __shfl_xor_sync(0xffffffffu, v, 4));
                    v = fmaxf(v, __shfl_xor_sync(0xffffffffu, v, 8));
                    v = fmaxf(v, __shfl_xor_sync(0xffffffffu, v, 16));
                    if (g == 0)
                        atomicMax(&g_maxbits[tj * 128 + wn * 32 + nt * 8 + q * 2 + e],
                                  __float_as_int(fmaxf(v + 2.0f, 0.0f)));
                }
        }

        if (n + 1 < MYT) {
            if (ti_n != ti) {
                flushRows(ti);
                __syncthreads();          // all warps done reading A
                loadA(ti_n);
                asm volatile("cp.async.commit_group;");
                loadLr(ti_n);
            }
            ti = ti_n; tj = tj_n;
        }
    }
    flushRows(ti);

    // ---- fused finalize: last CTA to arrive reduces the loss ----
    __threadfence();
    if (tid == 0) s_last = (atomicAdd(&g_done, 1) == GRID - 1) ? 1 : 0;
    __syncthreads();
    if (s_last) {
        float s = 0.0f;
        for (int i = tid; i < NB; i += 256) {
            float gmax = __int_as_float(__ldcg(&g_maxbits[i])) - 2.0f;
            float neg  = fmaxf(2.0f - 2.0f * gmax, 0.0f);
            float l    = __ldcg(&g_posd[i]) - neg + MARGIN;
            s += fmaxf(l, 0.0f);
        }
        red[tid] = s;
        __syncthreads();
        #pragma unroll
        for (int stride = 128; stride > 0; stride >>= 1) {
            if (tid < stride) red[tid] += red[tid + stride];
            __syncthreads();
        }
        if (tid == 0) out[0] = red[0] / (float)NB;
    }
}

extern "C" void kernel_launch(void* const* d_in, const int* in_sizes, int n_in,
                              void* d_out, int out_size) {
    const float* anchor   = (const float*)d_in[0];
    const float* positive = (const float*)d_in[1];
    const int*   labels   = (const int*)d_in[2];   // JAX x64 disabled: int64 -> int32
    float*       out      = (float*)d_out;

    prep_kernel<<<NB / 32, 256>>>(anchor, positive, labels);   // 4 rows per warp

    const int smem = 3 * TILE_BYTES;   // 104448 B -> 2 CTAs/SM
    cudaFuncSetAttribute(maxgram_sym, cudaFuncAttributeMaxDynamicSharedMemorySize, smem);
    maxgram_sym<<<GRID, 256, smem>>>(out);
}